// round 2
// baseline (speedup 1.0000x reference)
#include <cuda_runtime.h>

// Problem shape (fixed by reference)
#define BB 4
#define HH 16
#define SS 2048
#define DD 64
#define TQ 16          // queries per CTA
#define KC 256         // key chunk staged in smem
#define NTHREADS 512
#define SCALE 0.125f   // 1/sqrt(64)
#define NEGV -1000000000.0f

#define OUT_ELEMS (BB*HH*SS*DD)          // 8388608 floats: attention output
// weights follow at d_out + OUT_ELEMS  : B*H*S*S floats

// smem layout (floats):
//   scores [TQ][SS]          = 32768
//   KsT    [DD][KC] / Vs[KC][DD] = 16384
//   Qs     [TQ][DD] (outbuf in phase 3) = 1024
#define SMEM_FLOATS (TQ*SS + DD*KC + TQ*DD)
#define SMEM_BYTES  (SMEM_FLOATS * 4)

__global__ __launch_bounds__(NTHREADS, 1)
void sdpa_kernel(const float* __restrict__ Q, const float* __restrict__ K,
                 const float* __restrict__ V, const int* __restrict__ mask,
                 float* __restrict__ out, float* __restrict__ wts) {
    extern __shared__ float smem[];
    float* scores = smem;               // TQ * SS
    float* KsT    = smem + TQ*SS;       // DD * KC (phase1) / Vs[KC][DD] (phase3)
    float* Qs     = KsT + DD*KC;        // TQ * DD

    const int h  = blockIdx.x;
    const int q0 = blockIdx.y * TQ;
    const int b  = blockIdx.z;

    const int tid = threadIdx.x;
    const int w   = tid >> 5;
    const int l   = tid & 31;

    const size_t bh = (size_t)(b*HH + h);
    const float* Qb = Q + bh * SS * DD + (size_t)q0 * DD;
    const float* Kb = K + bh * SS * DD;
    const float* Vb = V + bh * SS * DD;
    const int*   Mb = mask + (size_t)b * SS * SS + (size_t)q0 * SS;
    float* Ob = out + bh * SS * DD + (size_t)q0 * DD;
    float* Wb = wts + bh * SS * SS + (size_t)q0 * SS;

    // load Q tile (sync provided by first chunk's post-load barrier)
    for (int i = tid; i < TQ*DD; i += NTHREADS) Qs[i] = Qb[i];

    const int qp = w & 7;     // query pair id: rows 2qp, 2qp+1
    const int kh = w >> 3;    // k-half within chunk: 0 or 1
    const int kposl = kh*128 + 4*l;

    // ================= Phase 1: scores = (Q K^T) * SCALE =================
    for (int kc = 0; kc < SS; kc += KC) {
        __syncthreads();   // protect KsT from previous chunk's readers
        // Stage K chunk transposed: KsT[d][k].
        // warp w owns d0 = 4w; lane l, iter i -> k = 32i + l.
        {
            const int d0 = 4*w;
            #pragma unroll
            for (int i = 0; i < KC/32; i++) {
                const int k = 32*i + l;
                float4 kv = *(const float4*)&Kb[(size_t)(kc + k)*DD + d0];
                KsT[(d0+0)*KC + k] = kv.x;
                KsT[(d0+1)*KC + k] = kv.y;
                KsT[(d0+2)*KC + k] = kv.z;
                KsT[(d0+3)*KC + k] = kv.w;
            }
        }
        __syncthreads();
        // Compute: 2 query rows x 4 consecutive keys per thread.
        float4 a0 = make_float4(0.f,0.f,0.f,0.f);
        float4 a1 = make_float4(0.f,0.f,0.f,0.f);
        const float* q0p = Qs + (2*qp)*DD;
        const float* q1p = Qs + (2*qp+1)*DD;
        const float* kbase = KsT + kposl;
        #pragma unroll
        for (int d = 0; d < DD; d++) {
            float4 kv = *(const float4*)&kbase[d*KC];
            float qa = q0p[d];
            float qb = q1p[d];
            a0.x = fmaf(qa, kv.x, a0.x); a0.y = fmaf(qa, kv.y, a0.y);
            a0.z = fmaf(qa, kv.z, a0.z); a0.w = fmaf(qa, kv.w, a0.w);
            a1.x = fmaf(qb, kv.x, a1.x); a1.y = fmaf(qb, kv.y, a1.y);
            a1.z = fmaf(qb, kv.z, a1.z); a1.w = fmaf(qb, kv.w, a1.w);
        }
        *(float4*)&scores[(2*qp)*SS + kc + kposl] =
            make_float4(a0.x*SCALE, a0.y*SCALE, a0.z*SCALE, a0.w*SCALE);
        *(float4*)&scores[(2*qp+1)*SS + kc + kposl] =
            make_float4(a1.x*SCALE, a1.y*SCALE, a1.z*SCALE, a1.w*SCALE);
    }
    __syncthreads();

    // ================= Phase 2: mask + softmax + write weights ==========
    {
        float4* srow4 = (float4*)(scores + w*SS);
        const int4* mrow4 = (const int4*)(Mb + (size_t)w*SS);
        float maxv = -3.0e38f;
        #pragma unroll 4
        for (int i = l; i < SS/4; i += 32) {
            float4 s = srow4[i];
            int4 m = mrow4[i];
            s.x = (m.x == 0) ? NEGV : s.x;
            s.y = (m.y == 0) ? NEGV : s.y;
            s.z = (m.z == 0) ? NEGV : s.z;
            s.w = (m.w == 0) ? NEGV : s.w;
            srow4[i] = s;
            maxv = fmaxf(maxv, fmaxf(fmaxf(s.x, s.y), fmaxf(s.z, s.w)));
        }
        #pragma unroll
        for (int o = 16; o; o >>= 1)
            maxv = fmaxf(maxv, __shfl_xor_sync(0xffffffffu, maxv, o));

        float sum = 0.f;
        #pragma unroll 4
        for (int i = l; i < SS/4; i += 32) {
            float4 s = srow4[i];
            s.x = __expf(s.x - maxv);
            s.y = __expf(s.y - maxv);
            s.z = __expf(s.z - maxv);
            s.w = __expf(s.w - maxv);
            srow4[i] = s;
            sum += (s.x + s.y) + (s.z + s.w);
        }
        #pragma unroll
        for (int o = 16; o; o >>= 1)
            sum += __shfl_xor_sync(0xffffffffu, sum, o);
        const float inv = 1.0f / sum;

        float4* wrow4 = (float4*)(Wb + (size_t)w * SS);
        #pragma unroll 4
        for (int i = l; i < SS/4; i += 32) {
            float4 s = srow4[i];
            s.x *= inv; s.y *= inv; s.z *= inv; s.w *= inv;
            srow4[i] = s;       // keep normalized p for phase 3
            wrow4[i] = s;       // stream weights to global
        }
    }
    __syncthreads();

    // ================= Phase 3: out = P @ V =============================
    float2 acc0 = make_float2(0.f, 0.f);
    float2 acc1 = make_float2(0.f, 0.f);
    const float* p0row = scores + (2*qp)*SS;
    const float* p1row = scores + (2*qp+1)*SS;
    float* Vs = KsT;   // reuse: natural layout Vs[k][d]
    for (int kc = 0; kc < SS; kc += KC) {
        __syncthreads();
        for (int i = tid*4; i < KC*DD; i += NTHREADS*4) {
            *(float4*)&Vs[i] = *(const float4*)&Vb[(size_t)kc*DD + i];
        }
        __syncthreads();
        const float* pr0 = p0row + kc + kh*128;
        const float* pr1 = p1row + kc + kh*128;
        const float* vsb = Vs + kh*128*DD + 2*l;
        #pragma unroll 8
        for (int k = 0; k < 128; k++) {
            float2 v = *(const float2*)&vsb[k*DD];
            float p0 = pr0[k];
            float p1 = pr1[k];
            acc0.x = fmaf(p0, v.x, acc0.x); acc0.y = fmaf(p0, v.y, acc0.y);
            acc1.x = fmaf(p1, v.x, acc1.x); acc1.y = fmaf(p1, v.y, acc1.y);
        }
    }
    // combine the two k-halves through smem (reuse Qs as outbuf[TQ][DD])
    float* outbuf = Qs;
    __syncthreads();
    if (kh == 0) {
        *(float2*)&outbuf[(2*qp)*DD   + 2*l] = acc0;
        *(float2*)&outbuf[(2*qp+1)*DD + 2*l] = acc1;
    }
    __syncthreads();
    if (kh == 1) {
        float2 b0 = *(const float2*)&outbuf[(2*qp)*DD   + 2*l];
        float2 b1 = *(const float2*)&outbuf[(2*qp+1)*DD + 2*l];
        acc0.x += b0.x; acc0.y += b0.y;
        acc1.x += b1.x; acc1.y += b1.y;
        *(float2*)&Ob[(size_t)(2*qp)*DD   + 2*l] = acc0;
        *(float2*)&Ob[(size_t)(2*qp+1)*DD + 2*l] = acc1;
    }
}

extern "C" void kernel_launch(void* const* d_in, const int* in_sizes, int n_in,
                              void* d_out, int out_size) {
    (void)in_sizes; (void)n_in; (void)out_size;
    const float* Q    = (const float*)d_in[0];
    const float* K    = (const float*)d_in[1];
    const float* V    = (const float*)d_in[2];
    const int*   mask = (const int*)d_in[3];
    float* out = (float*)d_out;
    float* wts = out + OUT_ELEMS;

    static int smem_set = 0;
    if (!smem_set) {
        cudaFuncSetAttribute(sdpa_kernel,
                             cudaFuncAttributeMaxDynamicSharedMemorySize,
                             SMEM_BYTES);
        smem_set = 1;
    }

    dim3 grid(HH, SS/TQ, BB);   // h fastest -> mask tile reused across heads in L2
    sdpa_kernel<<<grid, NTHREADS, SMEM_BYTES>>>(Q, K, V, mask, out, wts);
}